// round 13
// baseline (speedup 1.0000x reference)
#include <cuda_runtime.h>
#include <cstdint>
#include <math.h>

// ---------------- problem constants ----------------
#define T_TOK 16384
#define D_DIM 4096
#define E_EXP 256
#define G_GRP 8

// ---------------- GEMM tiling ----------------
#define BMI 64
#define BNI 128
#define KCI 32                    // k per stage (= one s8 k32 mma step)
#define NCHUNKI (D_DIM / KCI)     // 128
#define THREADS 512

// smem: rows padded to 48B (payload 32B). (3r+c16) mod 8 distinct -> ldmatrix conflict-free.
#define ROWI 48
#define APL (BMI * ROWI)          // 3072 per A plane
#define BPL (BNI * ROWI)          // 6144 per B plane
#define AOFF 0
#define BOFF (3 * APL)            // 9216
#define STG  (BOFF + 3 * BPL)     // 27648 per stage
#define SMEMI (2 * STG)           // 55296

// ---------------- scratch ----------------
__device__ float g_logits[T_TOK * E_EXP];   // 16.8 MB
__device__ char  g_w0[E_EXP * D_DIM];       // W digit 0 (2^0)
__device__ char  g_w1[E_EXP * D_DIM];       // W digit 1 (2^8)
__device__ char  g_w2[E_EXP * D_DIM];       // W digit 2 (2^16)
__device__ float g_colsum[E_EXP];
__device__ float g_count[E_EXP];

// ---------------- helpers ----------------
__device__ __forceinline__ uint32_t smem_u32(const void* p) {
    uint32_t a;
    asm("{ .reg .u64 t; cvta.to.shared.u64 t, %1; cvt.u32.u64 %0, t; }" : "=r"(a) : "l"(p));
    return a;
}
__device__ __forceinline__ void ldsm4(uint32_t* r, uint32_t addr) {
    asm volatile("ldmatrix.sync.aligned.m8n8.x4.shared.b16 {%0,%1,%2,%3}, [%4];"
                 : "=r"(r[0]), "=r"(r[1]), "=r"(r[2]), "=r"(r[3]) : "r"(addr));
}
__device__ __forceinline__ void ldsm2(uint32_t* r, uint32_t addr) {
    asm volatile("ldmatrix.sync.aligned.m8n8.x2.shared.b16 {%0,%1}, [%2];"
                 : "=r"(r[0]), "=r"(r[1]) : "r"(addr));
}
// exact: D s32 += A(16x32 s8) * B(32x8 s8)
__device__ __forceinline__ void mma_s8(int* d, const uint32_t* a, const uint32_t* b) {
    asm volatile(
        "mma.sync.aligned.m16n8k32.row.col.s32.s8.s8.s32 "
        "{%0,%1,%2,%3}, {%4,%5,%6,%7}, {%8,%9}, {%0,%1,%2,%3};"
        : "+r"(d[0]), "+r"(d[1]), "+r"(d[2]), "+r"(d[3])
        : "r"(a[0]), "r"(a[1]), "r"(a[2]), "r"(a[3]), "r"(b[0]), "r"(b[1]));
}
__device__ __forceinline__ void cp_async16(uint32_t saddr, const void* gaddr) {
    asm volatile("cp.async.cg.shared.global [%0], [%1], 16;" :: "r"(saddr), "l"(gaddr));
}
#define CP_COMMIT() asm volatile("cp.async.commit_group;")
#define CP_WAIT(N)  asm volatile("cp.async.wait_group %0;" :: "n"(N))

// signed base-256 digits of round(f*scale), |value| < 2^23 (exact for power-of-2 scale)
__device__ __forceinline__ void digits24(float f, float scale, int& d0, int& d1, int& d2) {
    int X = __float2int_rn(f * scale);
    d0 = (X << 24) >> 24;
    int r = (X - d0) >> 8;
    d1 = (r << 24) >> 24;
    d2 = (r - d1) >> 8;
}

// ---------------- kernel 0: zero accumulators ----------------
__global__ void zero_kernel() {
    int i = threadIdx.x;
    if (i < E_EXP) { g_colsum[i] = 0.0f; g_count[i] = 0.0f; }
}

// ---------------- kernel 0b: W -> 3 int8 digit planes (scale 2^26) ----------------
__global__ void wsplit_int(const float* __restrict__ W) {
    size_t i = (size_t)blockIdx.x * blockDim.x + threadIdx.x;   // float4 index
    float4 v = *(const float4*)(W + i * 4);
    float f[4] = {v.x, v.y, v.z, v.w};
    uint32_t p0 = 0, p1 = 0, p2 = 0;
#pragma unroll
    for (int j = 0; j < 4; ++j) {
        int d0, d1, d2;
        digits24(f[j], 67108864.0f, d0, d1, d2);   // 2^26
        p0 |= (uint32_t)(d0 & 0xFF) << (8 * j);
        p1 |= (uint32_t)(d1 & 0xFF) << (8 * j);
        p2 |= (uint32_t)(d2 & 0xFF) << (8 * j);
    }
    *(uint32_t*)&g_w0[i * 4] = p0;
    *(uint32_t*)&g_w1[i * 4] = p1;
    *(uint32_t*)&g_w2[i * 4] = p2;
}

// ---------------- kernel 1: exact int8-digit GEMM ----------------
// logits[t,e] = round_fp32( (sum_k X[t,k]*W[e,k]) * 2^-46 ), X=x*2^20, W=w*2^26 digits
__global__ __launch_bounds__(THREADS, 1)
void gemm_int8(const float* __restrict__ x) {
    extern __shared__ __align__(16) char smemc[];
    const uint32_t sb0 = smem_u32(smemc);

    const int tid  = threadIdx.x;
    const int lane = tid & 31;
    const int wid  = tid >> 5;
    const int wm   = wid & 3;     // m quarter: rows wm*16..+15
    const int wn   = wid >> 2;    // n quarter: cols wn*32..+31
    const int m0   = blockIdx.y * BMI;
    const int n0   = blockIdx.x * BNI;

    // acc[s-1]: exact int32 sums of digit-pair products with i+j == s  (s = 1..4)
    int ac[4][4][4];
#pragma unroll
    for (int g = 0; g < 4; ++g)
#pragma unroll
        for (int nt = 0; nt < 4; ++nt)
#pragma unroll
            for (int q = 0; q < 4; ++q) ac[g][nt][q] = 0;

    // A loader: thread -> row tid>>3 (0..63), 4 floats at k offset (tid&7)*4
    const int arow = tid >> 3;
    const int aoff = (tid & 7) * 4;
    const float* gx = x + (size_t)(m0 + arow) * D_DIM + aoff;
    const uint32_t asd = (uint32_t)(arow * ROWI + aoff);   // byte offset in plane

    // B loader: chunks c = tid (768 total: +256 extras for tid<256)
    const int c_a = tid;                       // planes 0,1
    const int pa = c_a >> 8, ra_ = (c_a & 255) >> 1, ka = (c_a & 1) * 16;
    const char* gba = (pa == 0 ? g_w0 : g_w1) + (size_t)(n0 + ra_) * D_DIM + ka;
    const uint32_t bda = (uint32_t)(BOFF + pa * BPL + ra_ * ROWI + ka);
    const int rb_ = (tid & 255) >> 1, kb = (tid & 1) * 16;  // plane 2 chunk (tid<256)
    const char* gbb = g_w2 + (size_t)(n0 + rb_) * D_DIM + kb;
    const uint32_t bdb = (uint32_t)(BOFF + 2 * BPL + rb_ * ROWI + kb);

    // fragment addresses
    const uint32_t a_base = (uint32_t)(AOFF + (wm * 16 + (lane & 15)) * ROWI + (lane >> 4) * 16);
    const uint32_t b_lane = (uint32_t)(((lane & 7)) * ROWI + ((lane >> 3) & 1) * 16);

    float4 ra;

    // ---- prologue: B stages 0,1 via cp.async; A chunk 0 via LDG ----
    {
        cp_async16(sb0 + bda, gba);
        if (tid < 256) cp_async16(sb0 + bdb, gbb);
        CP_COMMIT();
        cp_async16(sb0 + STG + bda, gba + KCI);
        if (tid < 256) cp_async16(sb0 + STG + bdb, gbb + KCI);
        CP_COMMIT();
        ra = *(const float4*)gx;
    }

#pragma unroll 1
    for (int i = 0; i < NCHUNKI; ++i) {
        const int s = i & 1;
        const uint32_t sA = sb0 + (uint32_t)(s * STG);

        // ---- convert + store A chunk i digits into stage s ----
        {
            float f[4] = {ra.x, ra.y, ra.z, ra.w};
            uint32_t p0 = 0, p1 = 0, p2 = 0;
#pragma unroll
            for (int j = 0; j < 4; ++j) {
                int d0, d1, d2;
                digits24(f[j], 1048576.0f, d0, d1, d2);   // 2^20
                p0 |= (uint32_t)(d0 & 0xFF) << (8 * j);
                p1 |= (uint32_t)(d1 & 0xFF) << (8 * j);
                p2 |= (uint32_t)(d2 & 0xFF) << (8 * j);
            }
            char* sb = smemc + s * STG;
            *(uint32_t*)(sb + AOFF + 0 * APL + asd) = p0;
            *(uint32_t*)(sb + AOFF + 1 * APL + asd) = p1;
            *(uint32_t*)(sb + AOFF + 2 * APL + asd) = p2;
        }
        // ---- prefetch A chunk i+1 ----
        if (i + 1 < NCHUNKI) ra = *(const float4*)(gx + (i + 1) * KCI);

        // ---- wait for B chunk i ----
        if (i + 1 < NCHUNKI) { CP_WAIT(1); } else { CP_WAIT(0); }
        __syncthreads();

        // ---- compute chunk i (one k32 step, 8 digit pairs) ----
        {
            uint32_t af[3][4];
#pragma unroll
            for (int p = 0; p < 3; ++p) ldsm4(af[p], sA + a_base + (uint32_t)(p * APL));
#pragma unroll
            for (int nt = 0; nt < 4; ++nt) {
                const uint32_t bb = sA + (uint32_t)(BOFF + (wn * 32 + nt * 8) * ROWI) + b_lane;
                uint32_t bf[3][2];
#pragma unroll
                for (int p = 0; p < 3; ++p) ldsm2(bf[p], bb + (uint32_t)(p * BPL));
                mma_s8(ac[3][nt], af[2], bf[2]);   // s=4
                mma_s8(ac[2][nt], af[2], bf[1]);   // s=3
                mma_s8(ac[2][nt], af[1], bf[2]);
                mma_s8(ac[1][nt], af[1], bf[1]);   // s=2
                mma_s8(ac[1][nt], af[2], bf[0]);
                mma_s8(ac[1][nt], af[0], bf[2]);
                mma_s8(ac[0][nt], af[1], bf[0]);   // s=1
                mma_s8(ac[0][nt], af[0], bf[1]);
            }
        }
        __syncthreads();

        // ---- issue B chunk i+2 into stage s ----
        if (i + 2 < NCHUNKI) {
            const int k0 = (i + 2) * KCI;
            cp_async16(sA + bda, gba + k0);
            if (tid < 256) cp_async16(sA + bdb, gbb + k0);
            CP_COMMIT();
        }
    }

    // ---- epilogue: exact fp64 recombination, round once to fp32 ----
#pragma unroll
    for (int nt = 0; nt < 4; ++nt) {
        const int ncol = n0 + wn * 32 + nt * 8 + (lane & 3) * 2;
        const int r0 = m0 + wm * 16 + (lane >> 2);
#pragma unroll
        for (int h = 0; h < 2; ++h) {   // c0,c1 (row) then c2,c3 (row+8)
            float v0 = (float)((double)ac[3][nt][2 * h + 0] * 0x1p-14 +
                               (double)ac[2][nt][2 * h + 0] * 0x1p-22 +
                               (double)ac[1][nt][2 * h + 0] * 0x1p-30 +
                               (double)ac[0][nt][2 * h + 0] * 0x1p-38);
            float v1 = (float)((double)ac[3][nt][2 * h + 1] * 0x1p-14 +
                               (double)ac[2][nt][2 * h + 1] * 0x1p-22 +
                               (double)ac[1][nt][2 * h + 1] * 0x1p-30 +
                               (double)ac[0][nt][2 * h + 1] * 0x1p-38);
            *(float2*)&g_logits[(size_t)(r0 + 8 * h) * E_EXP + ncol] = make_float2(v0, v1);
        }
    }
}

// ---------------- kernel 2: router epilogue (validated) ----------------
__device__ __forceinline__ bool better(float v, int i, float w, int j) {
    return (v > w) || (v == w && i < j);
}

__global__ __launch_bounds__(1024)
void router_kernel(float* __restrict__ out) {
    __shared__ float s_col[E_EXP];
    __shared__ float s_hist[E_EXP];
    const int tid = threadIdx.x;
    if (tid < E_EXP) { s_col[tid] = 0.0f; s_hist[tid] = 0.0f; }
    __syncthreads();

    const int warp = tid >> 5;
    const int lane = tid & 31;
    const int t = blockIdx.x * 32 + warp;
    const unsigned FULL = 0xFFFFFFFFu;

    float l[8];
    {
        const float* row = &g_logits[(size_t)t * E_EXP + lane * 8];
        *(float4*)&l[0] = *(const float4*)&row[0];
        *(float4*)&l[4] = *(const float4*)&row[4];
    }

    float m = l[0];
#pragma unroll
    for (int j = 1; j < 8; ++j) m = fmaxf(m, l[j]);
#pragma unroll
    for (int off = 16; off > 0; off >>= 1) m = fmaxf(m, __shfl_xor_sync(FULL, m, off));
    float p[8];
    float s = 0.0f;
#pragma unroll
    for (int j = 0; j < 8; ++j) { p[j] = expf(l[j] - m); s += p[j]; }
#pragma unroll
    for (int off = 16; off > 0; off >>= 1) s += __shfl_xor_sync(FULL, s, off);
    float invs = 1.0f / s;
#pragma unroll
    for (int j = 0; j < 8; ++j) p[j] *= invs;

#pragma unroll
    for (int j = 0; j < 8; ++j) atomicAdd(&s_col[lane * 8 + j], p[j]);

    float v1 = -1e30f, v2 = -1e30f;
    int i1 = 0, i2 = 0;
#pragma unroll
    for (int j = 0; j < 8; ++j) {
        int e = lane * 8 + j;
        if (p[j] > v1)      { v2 = v1; i2 = i1; v1 = p[j]; i1 = e; }
        else if (p[j] > v2) { v2 = p[j]; i2 = e; }
    }

#pragma unroll
    for (int d = 1; d <= 2; d <<= 1) {
        float w1 = __shfl_xor_sync(FULL, v1, d);
        int   k1 = __shfl_xor_sync(FULL, i1, d);
        float w2 = __shfl_xor_sync(FULL, v2, d);
        int   k2 = __shfl_xor_sync(FULL, i2, d);
        if (better(w1, k1, v1, i1)) {
            if (better(v1, i1, w2, k2)) { v2 = v1; i2 = i1; }
            else                        { v2 = w2; i2 = k2; }
            v1 = w1; i1 = k1;
        } else if (better(w1, k1, v2, i2)) {
            v2 = w1; i2 = k1;
        }
    }

    float gscore = v1 + v2;
    float gs[G_GRP];
#pragma unroll
    for (int g = 0; g < G_GRP; ++g) gs[g] = __shfl_sync(FULL, gscore, g * 4);

    int sel[4];
    bool used[G_GRP];
#pragma unroll
    for (int g = 0; g < G_GRP; ++g) used[g] = false;
    float wsum = 0.0f;
#pragma unroll
    for (int r = 0; r < 4; ++r) {
        int best = -1; float bv = -1e30f;
#pragma unroll
        for (int g = 0; g < G_GRP; ++g)
            if (!used[g] && gs[g] > bv) { bv = gs[g]; best = g; }
        sel[r] = best; used[best] = true; wsum += bv;
    }
    float invw = 1.0f / (wsum + 1e-9f);

    int rr  = lane & 3;
    int src = sel[rr] * 4;
    float fv1 = __shfl_sync(FULL, v1, src);
    int   fi1 = __shfl_sync(FULL, i1, src);
    float fv2 = __shfl_sync(FULL, v2, src);
    int   fi2 = __shfl_sync(FULL, i2, src);

    float* out_w = out;
    float* out_i = out + (size_t)T_TOK * 8;
    if (lane < 4) {
        size_t b = (size_t)t * 8 + 2 * lane;
        out_w[b]     = fv1 * invw;
        out_w[b + 1] = fv2 * invw;
        out_i[b]     = (float)fi1;
        out_i[b + 1] = (float)fi2;
    }
    if (lane == 0) atomicAdd(&s_hist[fi1], 1.0f);

    __syncthreads();
    if (tid < E_EXP) {
        atomicAdd(&g_colsum[tid], s_col[tid]);
        if (s_hist[tid] != 0.0f) atomicAdd(&g_count[tid], s_hist[tid]);
    }
}

// ---------------- kernel 3: aux loss ----------------
__global__ void aux_kernel(float* __restrict__ out) {
    __shared__ float red[8];
    int tid = threadIdx.x;
    float v = g_count[tid] * g_colsum[tid];
#pragma unroll
    for (int off = 16; off > 0; off >>= 1) v += __shfl_xor_sync(0xFFFFFFFFu, v, off);
    if ((tid & 31) == 0) red[tid >> 5] = v;
    __syncthreads();
    if (tid == 0) {
        float tot = 0.0f;
#pragma unroll
        for (int i = 0; i < 8; ++i) tot += red[i];
        out[(size_t)T_TOK * 16] = (float)E_EXP * tot / ((float)T_TOK * (float)T_TOK);
    }
}

// ---------------- launcher ----------------
extern "C" void kernel_launch(void* const* d_in, const int* in_sizes, int n_in,
                              void* d_out, int out_size) {
    const float* x = (const float*)d_in[0];
    const float* W = (const float*)d_in[1];
    float* out = (float*)d_out;

    cudaFuncSetAttribute(gemm_int8, cudaFuncAttributeMaxDynamicSharedMemorySize, SMEMI);

    zero_kernel<<<1, 256>>>();
    wsplit_int<<<(E_EXP * D_DIM / 4) / 256, 256>>>(W);
    gemm_int8<<<dim3(E_EXP / BNI, T_TOK / BMI), THREADS, SMEMI>>>(x);
    router_kernel<<<T_TOK / 32, 1024>>>(out);
    aux_kernel<<<1, 256>>>(out);
}

// round 14
// speedup vs baseline: 2.2168x; 2.2168x over previous
#include <cuda_runtime.h>
#include <cstdint>
#include <math.h>

// ---------------- problem constants ----------------
#define T_TOK 16384
#define D_DIM 4096
#define E_EXP 256
#define G_GRP 8

// ---------------- GEMM tiling ----------------
#define BM 256
#define BN 128
#define KC 32
#define NCHUNK (D_DIM / KC)      // 128
#define THREADS 512

// smem layout (bytes)
#define A_STRIDE 1040            // 256 floats + 16B pad
#define B_STRIDE 1280            // 16 blocks x 80B (64B dup payload + 16B pad)
#define A_BYTES (KC * A_STRIDE)  // 33280
#define B_BYTES (KC * B_STRIDE)  // 40960
#define STAGE_BYTES (A_BYTES + B_BYTES)   // 74240
#define SMEM_BYTES (2 * STAGE_BYTES)      // 148480

// ---------------- scratch ----------------
__device__ float g_logits[T_TOK * E_EXP];   // 16.8 MB
__device__ float g_colsum[E_EXP];
__device__ float g_count[E_EXP];

// ---------------- helpers ----------------
typedef unsigned long long ull;

__device__ __forceinline__ void fma2(ull& d, ull a, ull b) {
    asm("fma.rn.f32x2 %0, %1, %2, %0;" : "+l"(d) : "l"(a), "l"(b));
}
__device__ __forceinline__ ull dup2(float v) {
    ull r;
    asm("mov.b64 %0, {%1, %1};" : "=l"(r) : "f"(v));
    return r;
}
__device__ __forceinline__ void unpack2(ull v, float& lo, float& hi) {
    asm("mov.b64 {%0, %1}, %2;" : "=f"(lo), "=f"(hi) : "l"(v));
}

// ---------------- kernel 0: zero accumulators ----------------
__global__ void zero_kernel() {
    int i = threadIdx.x;
    if (i < E_EXP) { g_colsum[i] = 0.0f; g_count[i] = 0.0f; }
}

// ---------------- kernel 1: f32x2 FFMA GEMM (dup-B smem, 1 sync/chunk) ----------------
// logits[t,e] = sum_k x[t,k] * W[e,k]   (k-order identical to round-2 passing kernel)
__global__ __launch_bounds__(THREADS, 1)
void gemm_kernel(const float* __restrict__ x, const float* __restrict__ W) {
    extern __shared__ __align__(16) char smemc[];

    const int tid = threadIdx.x;
    const int tx = tid & 15;     // n octet (0..15)
    const int ty = tid >> 4;     // m octet (0..31)
    const int m0 = blockIdx.y * BM;
    const int n0 = blockIdx.x * BN;

    // acc[u][j]: f32x2 pair over rows (ty*8+2u, +1), col tx*8+j
    ull acc[4][8];
#pragma unroll
    for (int u = 0; u < 4; ++u)
#pragma unroll
        for (int j = 0; j < 8; ++j) acc[u][j] = 0ULL;

    float4 ra[4], rb[2];

    // ---- prologue: LDG chunk 0 ----
#pragma unroll
    for (int q = 0; q < 4; ++q) {
        int f = tid + q * 512;
        ra[q] = *(const float4*)&x[(size_t)(m0 + (f >> 3)) * D_DIM + (f & 7) * 4];
    }
#pragma unroll
    for (int q = 0; q < 2; ++q) {
        int f = tid + q * 512;
        rb[q] = *(const float4*)&W[(size_t)(n0 + (f >> 3)) * D_DIM + (f & 7) * 4];
    }

#pragma unroll 1
    for (int i = 0; i < NCHUNK; ++i) {
        char* sb = smemc + (i & 1) * STAGE_BYTES;

        // ---- STS chunk i (A transposed; B transposed + duplicated) ----
#pragma unroll
        for (int q = 0; q < 4; ++q) {
            int f = tid + q * 512;
            int m = f >> 3, kq = f & 7;
            float v[4] = {ra[q].x, ra[q].y, ra[q].z, ra[q].w};
#pragma unroll
            for (int j = 0; j < 4; ++j)
                *(float*)(sb + (kq * 4 + j) * A_STRIDE + m * 4) = v[j];
        }
#pragma unroll
        for (int q = 0; q < 2; ++q) {
            int f = tid + q * 512;
            int n = f >> 3, kq = f & 7;
            float v[4] = {rb[q].x, rb[q].y, rb[q].z, rb[q].w};
            uint32_t nb = (uint32_t)((n >> 3) * 80 + (n & 7) * 8);
#pragma unroll
            for (int j = 0; j < 4; ++j)
                *(ull*)(sb + A_BYTES + (kq * 4 + j) * B_STRIDE + nb) = dup2(v[j]);
        }
        __syncthreads();

        // ---- LDG chunk i+1 (hidden under compute) ----
        if (i + 1 < NCHUNK) {
            const int k0 = (i + 1) * KC;
#pragma unroll
            for (int q = 0; q < 4; ++q) {
                int f = tid + q * 512;
                ra[q] = *(const float4*)&x[(size_t)(m0 + (f >> 3)) * D_DIM + k0 + (f & 7) * 4];
            }
#pragma unroll
            for (int q = 0; q < 2; ++q) {
                int f = tid + q * 512;
                rb[q] = *(const float4*)&W[(size_t)(n0 + (f >> 3)) * D_DIM + k0 + (f & 7) * 4];
            }
        }

        // ---- compute chunk i ----
        {
            const char* sa = sb + ty * 32;
            const char* sbb = sb + A_BYTES + tx * 80;
#pragma unroll 8
            for (int k = 0; k < KC; ++k) {
                ulonglong2 aA = *(const ulonglong2*)(sa + k * A_STRIDE);
                ulonglong2 aB = *(const ulonglong2*)(sa + k * A_STRIDE + 16);
                ull ap[4] = {aA.x, aA.y, aB.x, aB.y};
                ulonglong2 b0 = *(const ulonglong2*)(sbb + k * B_STRIDE);
                ulonglong2 b1 = *(const ulonglong2*)(sbb + k * B_STRIDE + 16);
                ulonglong2 b2 = *(const ulonglong2*)(sbb + k * B_STRIDE + 32);
                ulonglong2 b3 = *(const ulonglong2*)(sbb + k * B_STRIDE + 48);
                ull bp[8] = {b0.x, b0.y, b1.x, b1.y, b2.x, b2.y, b3.x, b3.y};
#pragma unroll
                for (int u = 0; u < 4; ++u)
#pragma unroll
                    for (int j = 0; j < 8; ++j) fma2(acc[u][j], ap[u], bp[j]);
            }
        }
    }

    // ---- epilogue: write logits ----
#pragma unroll
    for (int u = 0; u < 4; ++u) {
        float lo[8], hi[8];
#pragma unroll
        for (int j = 0; j < 8; ++j) unpack2(acc[u][j], lo[j], hi[j]);
        size_t r0 = (size_t)(m0 + ty * 8 + 2 * u) * E_EXP + n0 + tx * 8;
        size_t r1 = r0 + E_EXP;
        *(float4*)&g_logits[r0]     = make_float4(lo[0], lo[1], lo[2], lo[3]);
        *(float4*)&g_logits[r0 + 4] = make_float4(lo[4], lo[5], lo[6], lo[7]);
        *(float4*)&g_logits[r1]     = make_float4(hi[0], hi[1], hi[2], hi[3]);
        *(float4*)&g_logits[r1 + 4] = make_float4(hi[4], hi[5], hi[6], hi[7]);
    }
}

// ---------------- kernel 2: router epilogue (validated) ----------------
__device__ __forceinline__ bool better(float v, int i, float w, int j) {
    return (v > w) || (v == w && i < j);
}

__global__ __launch_bounds__(1024)
void router_kernel(float* __restrict__ out) {
    __shared__ float s_col[E_EXP];
    __shared__ float s_hist[E_EXP];
    const int tid = threadIdx.x;
    if (tid < E_EXP) { s_col[tid] = 0.0f; s_hist[tid] = 0.0f; }
    __syncthreads();

    const int warp = tid >> 5;
    const int lane = tid & 31;
    const int t = blockIdx.x * 32 + warp;
    const unsigned FULL = 0xFFFFFFFFu;

    float l[8];
    {
        const float* row = &g_logits[(size_t)t * E_EXP + lane * 8];
        *(float4*)&l[0] = *(const float4*)&row[0];
        *(float4*)&l[4] = *(const float4*)&row[4];
    }

    float m = l[0];
#pragma unroll
    for (int j = 1; j < 8; ++j) m = fmaxf(m, l[j]);
#pragma unroll
    for (int off = 16; off > 0; off >>= 1) m = fmaxf(m, __shfl_xor_sync(FULL, m, off));
    float p[8];
    float s = 0.0f;
#pragma unroll
    for (int j = 0; j < 8; ++j) { p[j] = expf(l[j] - m); s += p[j]; }
#pragma unroll
    for (int off = 16; off > 0; off >>= 1) s += __shfl_xor_sync(FULL, s, off);
    float invs = 1.0f / s;
#pragma unroll
    for (int j = 0; j < 8; ++j) p[j] *= invs;

#pragma unroll
    for (int j = 0; j < 8; ++j) atomicAdd(&s_col[lane * 8 + j], p[j]);

    float v1 = -1e30f, v2 = -1e30f;
    int i1 = 0, i2 = 0;
#pragma unroll
    for (int j = 0; j < 8; ++j) {
        int e = lane * 8 + j;
        if (p[j] > v1)      { v2 = v1; i2 = i1; v1 = p[j]; i1 = e; }
        else if (p[j] > v2) { v2 = p[j]; i2 = e; }
    }

#pragma unroll
    for (int d = 1; d <= 2; d <<= 1) {
        float w1 = __shfl_xor_sync(FULL, v1, d);
        int   k1 = __shfl_xor_sync(FULL, i1, d);
        float w2 = __shfl_xor_sync(FULL, v2, d);
        int   k2 = __shfl_xor_sync(FULL, i2, d);
        if (better(w1, k1, v1, i1)) {
            if (better(v1, i1, w2, k2)) { v2 = v1; i2 = i1; }
            else                        { v2 = w2; i2 = k2; }
            v1 = w1; i1 = k1;
        } else if (better(w1, k1, v2, i2)) {
            v2 = w1; i2 = k1;
        }
    }

    float gscore = v1 + v2;
    float gs[G_GRP];
#pragma unroll
    for (int g = 0; g < G_GRP; ++g) gs[g] = __shfl_sync(FULL, gscore, g * 4);

    int sel[4];
    bool used[G_GRP];
#pragma unroll
    for (int g = 0; g < G_GRP; ++g) used[g] = false;
    float wsum = 0.0f;
#pragma unroll
    for (int r = 0; r < 4; ++r) {
        int best = -1; float bv = -1e30f;
#pragma unroll
        for (int g = 0; g < G_GRP; ++g)
            if (!used[g] && gs[g] > bv) { bv = gs[g]; best = g; }
        sel[r] = best; used[best] = true; wsum += bv;
    }
    float invw = 1.0f / (wsum + 1e-9f);

    int rr  = lane & 3;
    int src = sel[rr] * 4;
    float fv1 = __shfl_sync(FULL, v1, src);
    int   fi1 = __shfl_sync(FULL, i1, src);
    float fv2 = __shfl_sync(FULL, v2, src);
    int   fi2 = __shfl_sync(FULL, i2, src);

    float* out_w = out;
    float* out_i = out + (size_t)T_TOK * 8;
    if (lane < 4) {
        size_t b = (size_t)t * 8 + 2 * lane;
        out_w[b]     = fv1 * invw;
        out_w[b + 1] = fv2 * invw;
        out_i[b]     = (float)fi1;
        out_i[b + 1] = (float)fi2;
    }
    if (lane == 0) atomicAdd(&s_hist[fi1], 1.0f);

    __syncthreads();
    if (tid < E_EXP) {
        atomicAdd(&g_colsum[tid], s_col[tid]);
        if (s_hist[tid] != 0.0f) atomicAdd(&g_count[tid], s_hist[tid]);
    }
}

// ---------------- kernel 3: aux loss ----------------
__global__ void aux_kernel(float* __restrict__ out) {
    __shared__ float red[8];
    int tid = threadIdx.x;
    float v = g_count[tid] * g_colsum[tid];
#pragma unroll
    for (int off = 16; off > 0; off >>= 1) v += __shfl_xor_sync(0xFFFFFFFFu, v, off);
    if ((tid & 31) == 0) red[tid >> 5] = v;
    __syncthreads();
    if (tid == 0) {
        float tot = 0.0f;
#pragma unroll
        for (int i = 0; i < 8; ++i) tot += red[i];
        out[(size_t)T_TOK * 16] = (float)E_EXP * tot / ((float)T_TOK * (float)T_TOK);
    }
}

// ---------------- launcher ----------------
extern "C" void kernel_launch(void* const* d_in, const int* in_sizes, int n_in,
                              void* d_out, int out_size) {
    const float* x = (const float*)d_in[0];
    const float* W = (const float*)d_in[1];
    float* out = (float*)d_out;

    cudaFuncSetAttribute(gemm_kernel, cudaFuncAttributeMaxDynamicSharedMemorySize,
                         SMEM_BYTES);

    zero_kernel<<<1, 256>>>();
    gemm_kernel<<<dim3(E_EXP / BN, T_TOK / BM), THREADS, SMEM_BYTES>>>(x, W);
    router_kernel<<<T_TOK / 32, 1024>>>(out);
    aux_kernel<<<1, 256>>>(out);
}

// round 17
// speedup vs baseline: 2.2442x; 1.0123x over previous
#include <cuda_runtime.h>
#include <cstdint>
#include <math.h>

// ---------------- problem constants ----------------
#define T_TOK 16384
#define D_DIM 4096
#define E_EXP 256
#define G_GRP 8

// ---------------- GEMM tiling ----------------
// 74 M-strips (72x224 + 2x128) x 2 N-halves = 148 CTAs = one full wave on 148 SMs
#define BM_BIG 224
#define BN 128
#define KC 32
#define NCHUNK (D_DIM / KC)      // 128
#define THREADS 448

// smem layout (bytes)
#define A_STRIDE 912             // 224 floats + 16B pad
#define B_STRIDE 1280            // 16 blocks x 80B (64B dup payload + 16B pad)
#define A_BYTES (KC * A_STRIDE)  // 29184
#define B_BYTES (KC * B_STRIDE)  // 40960
#define STAGE_BYTES (A_BYTES + B_BYTES)   // 70144
#define SMEM_BYTES (2 * STAGE_BYTES)      // 140288

// ---------------- scratch ----------------
__device__ float g_logits[T_TOK * E_EXP];   // 16.8 MB
__device__ float g_colsum[E_EXP];
__device__ float g_count[E_EXP];

// ---------------- helpers ----------------
typedef unsigned long long ull;

__device__ __forceinline__ void fma2(ull& d, ull a, ull b) {
    asm("fma.rn.f32x2 %0, %1, %2, %0;" : "+l"(d) : "l"(a), "l"(b));
}
__device__ __forceinline__ ull dup2(float v) {
    ull r;
    asm("mov.b64 %0, {%1, %1};" : "=l"(r) : "f"(v));
    return r;
}
__device__ __forceinline__ void unpack2(ull v, float& lo, float& hi) {
    asm("mov.b64 {%0, %1}, %2;" : "=f"(lo), "=f"(hi) : "l"(v));
}

// ---------------- kernel 1: f32x2 FFMA GEMM, 148-CTA single wave ----------------
// logits[t,e] = sum_k x[t,k] * W[e,k]   (k-order identical to passing r14 kernel)
__global__ __launch_bounds__(THREADS, 1)
void gemm_kernel(const float* __restrict__ x, const float* __restrict__ W) {
    extern __shared__ __align__(16) char smemc[];

    const int tid = threadIdx.x;
    const int tx = tid & 15;     // n octet (0..15)
    const int ty = tid >> 4;     // m octet (0..27)
    const int bid = blockIdx.x;
    const int n0 = (bid & 1) * BN;
    const int strip = bid >> 1;  // 0..73
    const int m0    = (strip < 72) ? strip * BM_BIG : 16128 + (strip - 72) * 128;
    const int mrows = (strip < 72) ? BM_BIG : 128;

    // fold accumulator zeroing into the GEMM (runs before router)
    if (bid == 0 && tid < E_EXP) { g_colsum[tid] = 0.0f; g_count[tid] = 0.0f; }

    // acc[u][j]: f32x2 pair over rows (ty*8+2u, +1), col tx*8+j
    ull acc[4][8];
#pragma unroll
    for (int u = 0; u < 4; ++u)
#pragma unroll
        for (int j = 0; j < 8; ++j) acc[u][j] = 0ULL;

    float4 ra[4], rb[3];

    // A: 224*32/4 = 1792 float4 = 448*4 ; row = f>>3, kq = f&7 (guard rows for small strips)
    // B: 128*32/4 = 1024 float4 = 448*2 + 128 (third chunk: tid < 128 only)
    const int rA[4] = {
        (tid          ) >> 3, (tid +  448) >> 3, (tid +  896) >> 3, (tid + 1344) >> 3 };
    int rAg[4];
#pragma unroll
    for (int q = 0; q < 4; ++q) rAg[q] = (rA[q] < mrows) ? rA[q] : 0;

    // ---- prologue: LDG chunk 0 ----
#pragma unroll
    for (int q = 0; q < 4; ++q) {
        int f = tid + q * 448;
        ra[q] = *(const float4*)&x[(size_t)(m0 + rAg[q]) * D_DIM + (f & 7) * 4];
    }
#pragma unroll
    for (int q = 0; q < 2; ++q) {
        int f = tid + q * 448;
        rb[q] = *(const float4*)&W[(size_t)(n0 + (f >> 3)) * D_DIM + (f & 7) * 4];
    }
    if (tid < 128) {
        int f = tid + 896;
        rb[2] = *(const float4*)&W[(size_t)(n0 + (f >> 3)) * D_DIM + (f & 7) * 4];
    }

#pragma unroll 1
    for (int i = 0; i < NCHUNK; ++i) {
        char* sb = smemc + (i & 1) * STAGE_BYTES;

        // ---- STS chunk i (A transposed; B transposed + duplicated) ----
#pragma unroll
        for (int q = 0; q < 4; ++q) {
            int f = tid + q * 448;
            int kq = f & 7;
            float v[4] = {ra[q].x, ra[q].y, ra[q].z, ra[q].w};
#pragma unroll
            for (int j = 0; j < 4; ++j)
                *(float*)(sb + (kq * 4 + j) * A_STRIDE + rA[q] * 4) = v[j];
        }
#pragma unroll
        for (int q = 0; q < 2; ++q) {
            int f = tid + q * 448;
            int n = f >> 3, kq = f & 7;
            float v[4] = {rb[q].x, rb[q].y, rb[q].z, rb[q].w};
            uint32_t nb = (uint32_t)((n >> 3) * 80 + (n & 7) * 8);
#pragma unroll
            for (int j = 0; j < 4; ++j)
                *(ull*)(sb + A_BYTES + (kq * 4 + j) * B_STRIDE + nb) = dup2(v[j]);
        }
        if (tid < 128) {
            int f = tid + 896;
            int n = f >> 3, kq = f & 7;
            float v[4] = {rb[2].x, rb[2].y, rb[2].z, rb[2].w};
            uint32_t nb = (uint32_t)((n >> 3) * 80 + (n & 7) * 8);
#pragma unroll
            for (int j = 0; j < 4; ++j)
                *(ull*)(sb + A_BYTES + (kq * 4 + j) * B_STRIDE + nb) = dup2(v[j]);
        }
        __syncthreads();

        // ---- LDG chunk i+1 (hidden under compute) ----
        if (i + 1 < NCHUNK) {
            const int k0 = (i + 1) * KC;
#pragma unroll
            for (int q = 0; q < 4; ++q) {
                int f = tid + q * 448;
                ra[q] = *(const float4*)&x[(size_t)(m0 + rAg[q]) * D_DIM + k0 + (f & 7) * 4];
            }
#pragma unroll
            for (int q = 0; q < 2; ++q) {
                int f = tid + q * 448;
                rb[q] = *(const float4*)&W[(size_t)(n0 + (f >> 3)) * D_DIM + k0 + (f & 7) * 4];
            }
            if (tid < 128) {
                int f = tid + 896;
                rb[2] = *(const float4*)&W[(size_t)(n0 + (f >> 3)) * D_DIM + k0 + (f & 7) * 4];
            }
        }

        // ---- compute chunk i ----
        {
            const char* sa = sb + ty * 32;
            const char* sbb = sb + A_BYTES + tx * 80;
#pragma unroll 8
            for (int k = 0; k < KC; ++k) {
                ulonglong2 aA = *(const ulonglong2*)(sa + k * A_STRIDE);
                ulonglong2 aB = *(const ulonglong2*)(sa + k * A_STRIDE + 16);
                ull ap[4] = {aA.x, aA.y, aB.x, aB.y};
                ulonglong2 b0 = *(const ulonglong2*)(sbb + k * B_STRIDE);
                ulonglong2 b1 = *(const ulonglong2*)(sbb + k * B_STRIDE + 16);
                ulonglong2 b2 = *(const ulonglong2*)(sbb + k * B_STRIDE + 32);
                ulonglong2 b3 = *(const ulonglong2*)(sbb + k * B_STRIDE + 48);
                ull bp[8] = {b0.x, b0.y, b1.x, b1.y, b2.x, b2.y, b3.x, b3.y};
#pragma unroll
                for (int u = 0; u < 4; ++u)
#pragma unroll
                    for (int j = 0; j < 8; ++j) fma2(acc[u][j], ap[u], bp[j]);
            }
        }
        __syncthreads();
    }

    // ---- epilogue: write logits (guard small strips) ----
    if (ty * 8 + 7 < mrows) {
#pragma unroll
        for (int u = 0; u < 4; ++u) {
            float lo[8], hi[8];
#pragma unroll
            for (int j = 0; j < 8; ++j) unpack2(acc[u][j], lo[j], hi[j]);
            size_t r0 = (size_t)(m0 + ty * 8 + 2 * u) * E_EXP + n0 + tx * 8;
            size_t r1 = r0 + E_EXP;
            *(float4*)&g_logits[r0]     = make_float4(lo[0], lo[1], lo[2], lo[3]);
            *(float4*)&g_logits[r0 + 4] = make_float4(lo[4], lo[5], lo[6], lo[7]);
            *(float4*)&g_logits[r1]     = make_float4(hi[0], hi[1], hi[2], hi[3]);
            *(float4*)&g_logits[r1 + 4] = make_float4(hi[4], hi[5], hi[6], hi[7]);
        }
    }
}

// ---------------- kernel 2: router epilogue (validated) ----------------
__device__ __forceinline__ bool better(float v, int i, float w, int j) {
    return (v > w) || (v == w && i < j);
}

__global__ __launch_bounds__(1024)
void router_kernel(float* __restrict__ out) {
    __shared__ float s_col[E_EXP];
    __shared__ float s_hist[E_EXP];
    const int tid = threadIdx.x;
    if (tid < E_EXP) { s_col[tid] = 0.0f; s_hist[tid] = 0.0f; }
    __syncthreads();

    const int warp = tid >> 5;
    const int lane = tid & 31;
    const int t = blockIdx.x * 32 + warp;
    const unsigned FULL = 0xFFFFFFFFu;

    float l[8];
    {
        const float* row = &g_logits[(size_t)t * E_EXP + lane * 8];
        *(float4*)&l[0] = *(const float4*)&row[0];
        *(float4*)&l[4] = *(const float4*)&row[4];
    }

    float m = l[0];
#pragma unroll
    for (int j = 1; j < 8; ++j) m = fmaxf(m, l[j]);
#pragma unroll
    for (int off = 16; off > 0; off >>= 1) m = fmaxf(m, __shfl_xor_sync(FULL, m, off));
    float p[8];
    float s = 0.0f;
#pragma unroll
    for (int j = 0; j < 8; ++j) { p[j] = expf(l[j] - m); s += p[j]; }
#pragma unroll
    for (int off = 16; off > 0; off >>= 1) s += __shfl_xor_sync(FULL, s, off);
    float invs = 1.0f / s;
#pragma unroll
    for (int j = 0; j < 8; ++j) p[j] *= invs;

#pragma unroll
    for (int j = 0; j < 8; ++j) atomicAdd(&s_col[lane * 8 + j], p[j]);

    float v1 = -1e30f, v2 = -1e30f;
    int i1 = 0, i2 = 0;
#pragma unroll
    for (int j = 0; j < 8; ++j) {
        int e = lane * 8 + j;
        if (p[j] > v1)      { v2 = v1; i2 = i1; v1 = p[j]; i1 = e; }
        else if (p[j] > v2) { v2 = p[j]; i2 = e; }
    }

#pragma unroll
    for (int d = 1; d <= 2; d <<= 1) {
        float w1 = __shfl_xor_sync(FULL, v1, d);
        int   k1 = __shfl_xor_sync(FULL, i1, d);
        float w2 = __shfl_xor_sync(FULL, v2, d);
        int   k2 = __shfl_xor_sync(FULL, i2, d);
        if (better(w1, k1, v1, i1)) {
            if (better(v1, i1, w2, k2)) { v2 = v1; i2 = i1; }
            else                        { v2 = w2; i2 = k2; }
            v1 = w1; i1 = k1;
        } else if (better(w1, k1, v2, i2)) {
            v2 = w1; i2 = k1;
        }
    }

    float gscore = v1 + v2;
    float gs[G_GRP];
#pragma unroll
    for (int g = 0; g < G_GRP; ++g) gs[g] = __shfl_sync(FULL, gscore, g * 4);

    int sel[4];
    bool used[G_GRP];
#pragma unroll
    for (int g = 0; g < G_GRP; ++g) used[g] = false;
    float wsum = 0.0f;
#pragma unroll
    for (int r = 0; r < 4; ++r) {
        int best = -1; float bv = -1e30f;
#pragma unroll
        for (int g = 0; g < G_GRP; ++g)
            if (!used[g] && gs[g] > bv) { bv = gs[g]; best = g; }
        sel[r] = best; used[best] = true; wsum += bv;
    }
    float invw = 1.0f / (wsum + 1e-9f);

    int rr  = lane & 3;
    int src = sel[rr] * 4;
    float fv1 = __shfl_sync(FULL, v1, src);
    int   fi1 = __shfl_sync(FULL, i1, src);
    float fv2 = __shfl_sync(FULL, v2, src);
    int   fi2 = __shfl_sync(FULL, i2, src);

    float* out_w = out;
    float* out_i = out + (size_t)T_TOK * 8;
    if (lane < 4) {
        size_t b = (size_t)t * 8 + 2 * lane;
        out_w[b]     = fv1 * invw;
        out_w[b + 1] = fv2 * invw;
        out_i[b]     = (float)fi1;
        out_i[b + 1] = (float)fi2;
    }
    if (lane == 0) atomicAdd(&s_hist[fi1], 1.0f);

    __syncthreads();
    if (tid < E_EXP) {
        atomicAdd(&g_colsum[tid], s_col[tid]);
        if (s_hist[tid] != 0.0f) atomicAdd(&g_count[tid], s_hist[tid]);
    }
}

// ---------------- kernel 3: aux loss ----------------
__global__ void aux_kernel(float* __restrict__ out) {
    __shared__ float red[8];
    int tid = threadIdx.x;
    float v = g_count[tid] * g_colsum[tid];
#pragma unroll
    for (int off = 16; off > 0; off >>= 1) v += __shfl_xor_sync(0xFFFFFFFFu, v, off);
    if ((tid & 31) == 0) red[tid >> 5] = v;
    __syncthreads();
    if (tid == 0) {
        float tot = 0.0f;
#pragma unroll
        for (int i = 0; i < 8; ++i) tot += red[i];
        out[(size_t)T_TOK * 16] = (float)E_EXP * tot / ((float)T_TOK * (float)T_TOK);
    }
}

// ---------------- launcher ----------------
extern "C" void kernel_launch(void* const* d_in, const int* in_sizes, int n_in,
                              void* d_out, int out_size) {
    const float* x = (const float*)d_in[0];
    const float* W = (const float*)d_in[1];
    float* out = (float*)d_out;

    cudaFuncSetAttribute(gemm_kernel, cudaFuncAttributeMaxDynamicSharedMemorySize,
                         SMEM_BYTES);

    gemm_kernel<<<148, THREADS, SMEM_BYTES>>>(x, W);
    router_kernel<<<T_TOK / 32, 1024>>>(out);
    aux_kernel<<<1, 256>>>(out);
}